// round 6
// baseline (speedup 1.0000x reference)
#include <cuda_runtime.h>
#include <stdint.h>

#define BB 1024
#define TT 1024
#define KK 48
#define START_TAG 46
#define STOP_TAG 47
#define NEGV (-10000.0f)
#define PADV (-3.0e38f)
#define NT 32                  // one warp per sequence

// forward-variable scratch: [t][seq][tag] (row t = fv BEFORE step t), +1 pad row
__device__ __align__(16) float g_fv[(size_t)(TT + 1) * BB * KK];

#define ADD2(out, a, b) \
    asm("add.rn.f32x2 %0, %1, %2;" : "=l"(out) : "l"(a), "l"(b))
#define UNPK(lo, hi, in) \
    asm("mov.b64 {%0, %1}, %2;" : "=f"(lo), "=f"(hi) : "l"(in))

// monotone float -> ordered signed int (exact for all non-NaN floats)
__device__ __forceinline__ int fkey(float f) {
    int i = __float_as_int(f);
    return (i >= 0) ? i : (i ^ 0x7fffffff);
}

// exact argmax over 48 candidates: lane l holds index l (sa) and 32+l (sb, PADV
// for l>=16). Ties -> lowest index (matches jnp.argmax first occurrence).
__device__ __forceinline__ int argmax48(float sa, float sb, float* bout) {
    int ka = fkey(sa), kb = fkey(sb);
    int v = (ka > kb) ? ka : kb;
    int m;
    asm("redux.sync.max.s32 %0, %1, 0xffffffff;" : "=r"(m) : "r"(v));
    unsigned ba = __ballot_sync(0xffffffffu, ka == m);
    unsigned bb = __ballot_sync(0xffffffffu, kb == m);
    int idx = ba ? (__ffs((int)ba) - 1) : (31 + __ffs((int)bb));
    int mi = (m >= 0) ? m : (m ^ 0x7fffffff);
    *bout = __int_as_float(mi);
    return idx;
}

__global__ __launch_bounds__(NT)
void viterbi_kernel(const float* __restrict__ feats,
                    const float* __restrict__ trans,
                    float* __restrict__ out)
{
    __shared__ __align__(16) float fv_sh[2][KK];
    __shared__ __align__(16) float trans_sh[KK * KK];
    __shared__ uint8_t path_sh[TT];

    const int l   = threadIdx.x;
    const int seq = blockIdx.x;       // grid == BB
    const int c   = l & 1;            // half: prevs [c*24, c*24+24)
    const int tb  = l >> 1;           // owned tags: tb, 16+tb, 32+tb

    // 72 transition entries as 36 packed f32x2 registers (pairs match fv pairs)
    unsigned long long trp[3][12];
#pragma unroll
    for (int u = 0; u < 3; u++) {
        const unsigned long long* tp =
            (const unsigned long long*)(trans + (16 * u + tb) * KK + c * 24);
#pragma unroll
        for (int k = 0; k < 12; k++) trp[u][k] = tp[k];
    }

    for (int i = l; i < KK; i += NT)
        fv_sh[0][i] = (i == START_TAG) ? 0.0f : NEGV;
    __syncwarp();

    const float* fb = feats + (size_t)seq * TT * KK + tb;
    float fn0 = fb[0], fn1 = fb[16], fn2 = fb[32];
    float* sbase = g_fv + (size_t)seq * KK;

    // ---------------- forward pass: max-only, warp-synchronous ----------------
    int buf = 0;
    for (int t = 0; t < TT; t++) {
        float f0 = fn0, f1 = fn1, f2 = fn2;
        int tn = (t + 1 < TT) ? (t + 1) : (TT - 1);
        const float* fnb = fb + (size_t)tn * KK;
        fn0 = fnb[0]; fn1 = fnb[16]; fn2 = fnb[32];

        const ulonglong2* fvr =
            reinterpret_cast<const ulonglong2*>(&fv_sh[buf][c * 24]);
        float m[3][4];
        {
            ulonglong2 w = fvr[0];
#pragma unroll
            for (int u = 0; u < 3; u++) {
                unsigned long long s0, s1;
                ADD2(s0, w.x, trp[u][0]);
                ADD2(s1, w.y, trp[u][1]);
                UNPK(m[u][0], m[u][1], s0);
                UNPK(m[u][2], m[u][3], s1);
            }
        }
#pragma unroll
        for (int q = 1; q < 6; q++) {
            ulonglong2 w = fvr[q];
#pragma unroll
            for (int u = 0; u < 3; u++) {
                unsigned long long s0, s1;
                float a, b2, c2, d2;
                ADD2(s0, w.x, trp[u][2 * q]);
                ADD2(s1, w.y, trp[u][2 * q + 1]);
                UNPK(a, b2, s0);
                UNPK(c2, d2, s1);
                m[u][0] = fmaxf(m[u][0], a);
                m[u][1] = fmaxf(m[u][1], b2);
                m[u][2] = fmaxf(m[u][2], c2);
                m[u][3] = fmaxf(m[u][3], d2);
            }
        }
        float r0 = fmaxf(fmaxf(m[0][0], m[0][1]), fmaxf(m[0][2], m[0][3]));
        float r1 = fmaxf(fmaxf(m[1][0], m[1][1]), fmaxf(m[1][2], m[1][3]));
        float r2 = fmaxf(fmaxf(m[2][0], m[2][1]), fmaxf(m[2][2], m[2][3]));
        r0 = fmaxf(r0, __shfl_xor_sync(0xffffffffu, r0, 1));
        r1 = fmaxf(r1, __shfl_xor_sync(0xffffffffu, r1, 1));
        r2 = fmaxf(r2, __shfl_xor_sync(0xffffffffu, r2, 1));
        if (c == 0) {
            float v0 = r0 + f0, v1 = r1 + f1, v2 = r2 + f2;
            float* fnxt = fv_sh[buf ^ 1];
            fnxt[tb] = v0; fnxt[16 + tb] = v1; fnxt[32 + tb] = v2;
            float* sr = sbase + (size_t)(t + 1) * (BB * KK);
            sr[tb] = v0; sr[16 + tb] = v1; sr[32 + tb] = v2;
        }
        __syncwarp();
        buf ^= 1;
    }

    // stage transitions for backtrack (L2-hot: every block reads same 9KB)
    for (int i = l; i < (KK * KK) / 4; i += NT)
        reinterpret_cast<float4*>(trans_sh)[i] =
            reinterpret_cast<const float4*>(trans)[i];
    __syncwarp();

    // ---------------- terminal + backtrack ----------------
    {
        float fa = fv_sh[buf][l];
        float fb2 = (l < 16) ? fv_sh[buf][32 + l] : 0.0f;
        float sa = fa + trans_sh[STOP_TAG * KK + l];
        float sb = (l < 16) ? (fb2 + trans_sh[STOP_TAG * KK + 32 + l]) : PADV;
        float best;
        int tag = argmax48(sa, sb, &best);
        if (l == 0) out[seq] = best;

        const float* rowbase = g_fv + (size_t)seq * KK;
        const size_t RSTR = (size_t)BB * KK;
        float a0 = rowbase[(size_t)(TT - 1) * RSTR + l];
        float e0 = (l < 16) ? rowbase[(size_t)(TT - 1) * RSTR + 32 + l] : 0.0f;
        float a1 = rowbase[(size_t)(TT - 2) * RSTR + l];
        float e1 = (l < 16) ? rowbase[(size_t)(TT - 2) * RSTR + 32 + l] : 0.0f;
        float a2 = rowbase[(size_t)(TT - 3) * RSTR + l];
        float e2 = (l < 16) ? rowbase[(size_t)(TT - 3) * RSTR + 32 + l] : 0.0f;

#define BT_STEP(T_, AA, EE, PF)                                              \
        {                                                                    \
            if (l == 0) path_sh[(T_)] = (uint8_t)tag;                        \
            float s_a = AA + trans_sh[tag * KK + l];                         \
            float s_b = (l < 16) ? (EE + trans_sh[tag * KK + 32 + l]) : PADV;\
            int rpf = ((PF) < 1) ? 1 : (PF);                                 \
            AA = rowbase[(size_t)rpf * RSTR + l];                            \
            EE = (l < 16) ? rowbase[(size_t)rpf * RSTR + 32 + l] : 0.0f;     \
            float bv;                                                        \
            tag = argmax48(s_a, s_b, &bv);                                   \
        }

        for (int t = TT - 1; t >= 3; t -= 3) {   // 1023 steps, divisible by 3
            BT_STEP(t,     a0, e0, t - 3)
            BT_STEP(t - 1, a1, e1, t - 4)
            BT_STEP(t - 2, a2, e2, t - 5)
        }
        if (l == 0) path_sh[0] = (uint8_t)tag;
#undef BT_STEP
    }
    __syncwarp();

    // ---------------- coalesced path dump ----------------
    float* pout = out + BB + (size_t)seq * TT;
    for (int t = l; t < TT; t += NT) pout[t] = (float)path_sh[t];
}

extern "C" void kernel_launch(void* const* d_in, const int* in_sizes, int n_in,
                              void* d_out, int out_size) {
    (void)in_sizes; (void)n_in; (void)out_size;
    const float* feats = (const float*)d_in[0];
    const float* trans = (const float*)d_in[1];
    float* out = (float*)d_out;
    viterbi_kernel<<<BB, NT>>>(feats, trans, out);
}